// round 7
// baseline (speedup 1.0000x reference)
#include <cuda_runtime.h>
#include <cuda_fp16.h>
#include <cstdint>

#define BATCH 8
#define NNODE 2048
#define NEDGE 65536
#define HDIM  128
#define NRAD  6
#define TILE_E 128

typedef unsigned long long u64;

// ---------------- device globals (no allocation) ----------------
__device__ float g_u1[HDIM];
__device__ float g_u2[HDIM];
__device__ float g_c[HDIM];
// W3 (lin_w[:,256:384]) as fp16, mma.m16n8k16 A-fragment order:
// index ((tm*8 + tk)*32 + lane) -> uint4 = {a0,a1,a2,a3}
__device__ uint4 g_WA[8 * 8 * 32];

// ---------------- smem byte offsets ----------------
// OFF_B: B fragments (32768 B). After MMA this region (plus OFF_RBF) is
// reused as the 64x132-float epilogue stage buffer (33792 B).
#define OFF_B    0
#define OFF_RBF  32768    // rbf tile [128][8] f32 (padded): 4096 B
#define OFF_XI   36864    // 512 B  (live through epilogue)
#define OFF_XJ   37376    // 512 B
#define SMEM_BYTES 37888
#define STAGE_ROW 132     // floats per stage row (128 + 4 pad)

// ---------------- helpers ----------------
__device__ __forceinline__ uint32_t smem_u32(const void* p) {
    uint32_t a;
    asm("{ .reg .u64 t; cvta.to.shared.u64 t, %1; cvt.u32.u64 %0, t; }" : "=r"(a) : "l"(p));
    return a;
}
__device__ __forceinline__ uint4 lds128(uint32_t addr) {
    uint4 v;
    asm volatile("ld.shared.v4.b32 {%0,%1,%2,%3}, [%4];"
                 : "=r"(v.x), "=r"(v.y), "=r"(v.z), "=r"(v.w) : "r"(addr));
    return v;
}
__device__ __forceinline__ void sts64(uint32_t addr, u64 v) {
    asm volatile("st.shared.b64 [%0], %1;" :: "r"(addr), "l"(v) : "memory");
}
__device__ __forceinline__ void sts32f(uint32_t addr, float v) {
    asm volatile("st.shared.b32 [%0], %1;" :: "r"(addr), "f"(v) : "memory");
}
// packed f16x2: low half <- lo, high half <- hi
__device__ __forceinline__ uint32_t cvt_f16x2(float lo, float hi) {
    uint32_t d;
    asm("cvt.rn.f16x2.f32 %0, %2, %1;" : "=r"(d) : "f"(lo), "f"(hi));
    return d;
}
__device__ __forceinline__ void mma16816(float* d, uint32_t a0, uint32_t a1,
                                         uint32_t a2, uint32_t a3,
                                         uint32_t b0, uint32_t b1) {
    asm volatile(
        "mma.sync.aligned.m16n8k16.row.col.f32.f16.f16.f32 "
        "{%0,%1,%2,%3}, {%4,%5,%6,%7}, {%8,%9}, {%0,%1,%2,%3};"
        : "+f"(d[0]), "+f"(d[1]), "+f"(d[2]), "+f"(d[3])
        : "r"(a0), "r"(a1), "r"(a2), "r"(a3), "r"(b0), "r"(b1));
}
// silu via single-MUFU tanh: z*sigmoid(z) = 0.5z + 0.5z*tanh(0.5z)
__device__ __forceinline__ float silu_t(float z) {
    float h = 0.5f * z;
    float t;
    asm("tanh.approx.f32 %0, %1;" : "=f"(t) : "f"(h));
    return fmaf(h, t, h);
}

// ---------------------------------------------------------------------------
// Single precompute kernel (2 launches/replay keeps ncu -s 5 on edge_mlp).
// ---------------------------------------------------------------------------
__global__ void precompute_all(const float* __restrict__ emb_w,
                               const float* __restrict__ emb_b,
                               const float* __restrict__ lin_w,
                               const float* __restrict__ lin_b) {
    __shared__ float red[2][3][4];
    const int tid = threadIdx.x;
    const int bid = blockIdx.x;

    // ---- part A: u1/u2/c ----
    {
        const int half = tid >> 7;
        const int o = bid * 2 + half;
        const int h = tid & 127;
        float w1 = lin_w[o * (3 * HDIM) + h];
        float w2 = lin_w[o * (3 * HDIM) + HDIM + h];
        float u1 = w1 * emb_w[h];
        float u2 = w2 * emb_w[h];
        float cc = (w1 + w2) * emb_b[h];
        #pragma unroll
        for (int s = 16; s > 0; s >>= 1) {
            u1 += __shfl_down_sync(0xffffffff, u1, s);
            u2 += __shfl_down_sync(0xffffffff, u2, s);
            cc += __shfl_down_sync(0xffffffff, cc, s);
        }
        const int w4 = (tid >> 5) & 3;
        if ((tid & 31) == 0) {
            red[half][0][w4] = u1; red[half][1][w4] = u2; red[half][2][w4] = cc;
        }
        __syncthreads();
        if ((tid & 127) == 0) {
            g_u1[o] = red[half][0][0] + red[half][0][1] + red[half][0][2] + red[half][0][3];
            g_u2[o] = red[half][1][0] + red[half][1][1] + red[half][1][2] + red[half][1][3];
            g_c[o]  = red[half][2][0] + red[half][2][1] + red[half][2][2] + red[half][2][3]
                      + lin_b[o];
        }
    }

    // ---- part B: W3 fp16 A-fragment pack ----
    const int idx = bid * 256 + tid;
    if (idx < 2048) {
        const int lane = idx & 31;
        const int t    = idx >> 5;
        const int tk   = t & 7;
        const int tm   = t >> 3;
        const int o0 = tm * 16 + (lane >> 2);
        const int o1 = o0 + 8;
        const int k0 = tk * 16 + (lane & 3) * 2;

        const float* base = lin_w + 2 * HDIM;
        uint32_t a0 = cvt_f16x2(base[o0 * (3 * HDIM) + k0],     base[o0 * (3 * HDIM) + k0 + 1]);
        uint32_t a1 = cvt_f16x2(base[o1 * (3 * HDIM) + k0],     base[o1 * (3 * HDIM) + k0 + 1]);
        uint32_t a2 = cvt_f16x2(base[o0 * (3 * HDIM) + k0 + 8], base[o0 * (3 * HDIM) + k0 + 9]);
        uint32_t a3 = cvt_f16x2(base[o1 * (3 * HDIM) + k0 + 8], base[o1 * (3 * HDIM) + k0 + 9]);
        g_WA[idx] = make_uint4(a0, a1, a2, a3);
    }
}

// ---------------------------------------------------------------------------
// Main fused kernel
//
// B layout (fp16 r fragments), kt-paired + parity swizzle:
//   pair p = kt>>1, chunk C2 = (e>>3)*4 + p  (64 chunks x 512B)
//   word w = (e&7)*4 + q  (16B words; bytes 0-7 = kt even, 8-15 = kt odd)
//   addr = C2*512 + ((w*16) ^ ((p&1)<<6)) + (kt&1)*8
//   -> store: 2-phase (optimal); load: one LDS.128 feeds two MMAs.
// ---------------------------------------------------------------------------
__global__ void __launch_bounds__(256, 2)
edge_mlp_kernel(const float* __restrict__ x,
                const float* __restrict__ rbf,
                const int* __restrict__ iidx,
                const int* __restrict__ jidx,
                const float* __restrict__ rbf_w,
                const float* __restrict__ rbf_b,
                float* __restrict__ out) {
    extern __shared__ char sm[];
    const uint32_t sb = smem_u32(sm);

    const int b    = blockIdx.y;
    const int e0   = blockIdx.x * TILE_E;
    const int tid  = threadIdx.x;
    const int wid  = tid >> 5;
    const int lane = tid & 31;

    float* rbf_s = (float*)(sm + OFF_RBF);   // [128][8] padded
    float* xi_s  = (float*)(sm + OFF_XI);
    float* xj_s  = (float*)(sm + OFF_XJ);

    // ---- stage rbf tile into padded rows [e][8] ----
    {
        const float* src = rbf + ((size_t)b * NEDGE + e0) * NRAD;
        #pragma unroll
        for (int it = 0; it < 3; ++it) {
            int idx = tid + it * 256;        // 0..767
            int e = idx / NRAD, m = idx - e * NRAD;
            rbf_s[e * 8 + m] = src[idx];
        }
    }
    // ---- gather x_i / x_j (int32 indices; mask so bad index cannot fault) ----
    if (tid < 128) {
        int e = e0 + tid;
        int ii = iidx[e] & (NNODE - 1);
        int jj = jidx[e] & (NNODE - 1);
        xi_s[tid] = x[b * NNODE + ii];
        xj_s[tid] = x[b * NNODE + jj];
    }
    __syncthreads();

    // ---- r-phase: lane owns 4 k-channels (kb,kb+1,kb+8,kb+9); 16 edges ----
    {
        const int kt = lane >> 2;        // 0..7
        const int q  = lane & 3;         // 0..3
        const int p  = kt >> 1;          // pair 0..3
        const int ph = kt & 1;           // half within pair
        const uint32_t swz = (uint32_t)((p & 1) << 6);
        const int kb = kt * 16 + q * 2;
        const int ks[4] = { kb, kb + 1, kb + 8, kb + 9 };

        float rw[4][NRAD], rb4[4];
        #pragma unroll
        for (int kk = 0; kk < 4; ++kk) {
            rb4[kk] = __ldg(rbf_b + ks[kk]);
            #pragma unroll
            for (int m = 0; m < NRAD; ++m)
                rw[kk][m] = __ldg(rbf_w + ks[kk] * NRAD + m);
        }

        const int ebase = wid * 16;
        #pragma unroll 2
        for (int t = 0; t < 16; ++t) {
            const int e = ebase + t;
            const float4 r03 = *(const float4*)(rbf_s + e * 8);
            const float2 r45 = *(const float2*)(rbf_s + e * 8 + 4);
            const float rv[NRAD] = { r03.x, r03.y, r03.z, r03.w, r45.x, r45.y };

            float z[4];
            #pragma unroll
            for (int kk = 0; kk < 4; ++kk) {
                z[kk] = rb4[kk];
                #pragma unroll
                for (int m = 0; m < NRAD; ++m)
                    z[kk] = fmaf(rv[m], rw[kk][m], z[kk]);
            }
            uint32_t b01 = cvt_f16x2(silu_t(z[0]), silu_t(z[1]));
            uint32_t b23 = cvt_f16x2(silu_t(z[2]), silu_t(z[3]));

            const uint32_t C2 = (uint32_t)(((e >> 3) * 4 + p));
            const uint32_t w  = (uint32_t)(((e & 7) * 4 + q));
            uint32_t addr = sb + OFF_B + C2 * 512 + ((w * 16) ^ swz) + ph * 8;
            sts64(addr, (u64)b01 | ((u64)b23 << 32));
        }
    }
    __syncthreads();

    // ---- mma: warp tile 32(o) x 64(e) ----
    const int wm  = wid & 3;    // o-group: rows wm*32..+31
    const int wng = wid >> 2;   // e-group: cols wng*64..+63

    float acc[2][8][4];
    #pragma unroll
    for (int i = 0; i < 2; ++i)
        #pragma unroll
        for (int j = 0; j < 8; ++j)
            #pragma unroll
            for (int q = 0; q < 4; ++q) acc[i][j][q] = 0.f;

    #pragma unroll
    for (int p = 0; p < 4; ++p) {
        const int kt0 = 2 * p, kt1 = 2 * p + 1;
        uint4 a0e = __ldg(g_WA + ((wm * 2 + 0) * 8 + kt0) * 32 + lane);
        uint4 a0o = __ldg(g_WA + ((wm * 2 + 0) * 8 + kt1) * 32 + lane);
        uint4 a1e = __ldg(g_WA + ((wm * 2 + 1) * 8 + kt0) * 32 + lane);
        uint4 a1o = __ldg(g_WA + ((wm * 2 + 1) * 8 + kt1) * 32 + lane);
        const uint32_t swz = (uint32_t)((p & 1) << 6);
        #pragma unroll
        for (int j = 0; j < 8; ++j) {
            const uint32_t C2 = (uint32_t)(((wng * 8 + j) * 4 + p));
            uint4 v = lds128(sb + OFF_B + C2 * 512 + (((uint32_t)lane * 16) ^ swz));
            mma16816(acc[0][j], a0e.x, a0e.y, a0e.z, a0e.w, v.x, v.y);
            mma16816(acc[0][j], a0o.x, a0o.y, a0o.z, a0o.w, v.z, v.w);
            mma16816(acc[1][j], a1e.x, a1e.y, a1e.z, a1e.w, v.x, v.y);
            mma16816(acc[1][j], a1o.x, a1o.y, a1o.z, a1o.w, v.z, v.w);
        }
    }

    // ---- epilogue constants ----
    float u1v[2][2], u2v[2][2], cv[2][2];
    #pragma unroll
    for (int i = 0; i < 2; ++i) {
        int ob = wm * 32 + i * 16 + (lane >> 2);
        u1v[i][0] = __ldg(g_u1 + ob);     u1v[i][1] = __ldg(g_u1 + ob + 8);
        u2v[i][0] = __ldg(g_u2 + ob);     u2v[i][1] = __ldg(g_u2 + ob + 8);
        cv[i][0]  = __ldg(g_c + ob);      cv[i][1]  = __ldg(g_c + ob + 8);
    }

    // ---- staged epilogue: two e-halves of 64 rows through smem ----
    // stage buffer overlays OFF_B/OFF_RBF (both dead after the mma loop).
    __syncthreads();   // all B reads done before stage overwrites

    float* outb = out + ((size_t)b * NEDGE + e0) * HDIM;
    #pragma unroll
    for (int eh = 0; eh < 2; ++eh) {
        if (wng == eh) {
            #pragma unroll
            for (int j = 0; j < 8; ++j) {
                const int el = j * 8 + (lane & 3) * 2;       // row within half
                const int eg = eh * 64 + el;                 // global edge in tile
                const float2 xiv = *(const float2*)(xi_s + eg);
                const float2 xjv = *(const float2*)(xj_s + eg);
                #pragma unroll
                for (int i = 0; i < 2; ++i) {
                    const int ob = wm * 32 + i * 16 + (lane >> 2);
                    #pragma unroll
                    for (int h = 0; h < 2; ++h) {
                        float p0 = acc[i][j][h * 2 + 0];
                        float p1 = acc[i][j][h * 2 + 1];
                        p0 = fmaf(xiv.x, u1v[i][h], p0);
                        p0 = fmaf(xjv.x, u2v[i][h], p0) + cv[i][h];
                        p1 = fmaf(xiv.y, u1v[i][h], p1);
                        p1 = fmaf(xjv.y, u2v[i][h], p1) + cv[i][h];
                        const int oo = ob + h * 8;
                        sts32f(sb + (uint32_t)((el * STAGE_ROW + oo) * 4),       silu_t(p0));
                        sts32f(sb + (uint32_t)(((el + 1) * STAGE_ROW + oo) * 4), silu_t(p1));
                    }
                }
            }
        }
        __syncthreads();
        // all threads: coalesced copy 64 rows x 128 floats -> gmem
        const float* stg = (const float*)sm;
        #pragma unroll
        for (int it = 0; it < 8; ++it) {
            const int idx = tid + it * 256;      // 0..2047
            const int row = idx >> 5;
            const int c4  = idx & 31;
            float4 v = *(const float4*)(stg + row * STAGE_ROW + c4 * 4);
            *(float4*)(outb + (size_t)(eh * 64 + row) * HDIM + c4 * 4) = v;
        }
        __syncthreads();
    }
}

// ---------------------------------------------------------------------------
extern "C" void kernel_launch(void* const* d_in, const int* in_sizes, int n_in,
                              void* d_out, int out_size) {
    const float* x     = (const float*)d_in[0];
    const float* rbf   = (const float*)d_in[1];
    const int*   iidx  = (const int*)d_in[2];   // int32 (JAX x64 disabled)
    const int*   jidx  = (const int*)d_in[3];
    const float* emb_w = (const float*)d_in[4];
    const float* emb_b = (const float*)d_in[5];
    const float* rbf_w = (const float*)d_in[6];
    const float* rbf_b = (const float*)d_in[7];
    const float* lin_w = (const float*)d_in[8];
    const float* lin_b = (const float*)d_in[9];
    float* out = (float*)d_out;

    precompute_all<<<64, 256>>>(emb_w, emb_b, lin_w, lin_b);

    cudaFuncSetAttribute(edge_mlp_kernel,
                         cudaFuncAttributeMaxDynamicSharedMemorySize, SMEM_BYTES);
    dim3 grid(NEDGE / TILE_E, BATCH);   // (512, 8)
    edge_mlp_kernel<<<grid, 256, SMEM_BYTES>>>(x, rbf, iidx, jidx, rbf_w, rbf_b, out);
}

// round 8
// speedup vs baseline: 1.6644x; 1.6644x over previous
#include <cuda_runtime.h>
#include <cuda_fp16.h>
#include <cstdint>

#define BATCH 8
#define NNODE 2048
#define NEDGE 65536
#define HDIM  128
#define NRAD  6
#define TILE_E 128

typedef unsigned long long u64;

// ---------------- device globals (no allocation) ----------------
__device__ float g_u1[HDIM];
__device__ float g_u2[HDIM];
__device__ float g_c[HDIM];
// W3 (lin_w[:,256:384]) as fp16, mma.m16n8k16 A-fragment order:
// index ((tm*8 + tk)*32 + lane) -> uint4 = {a0,a1,a2,a3}
__device__ uint4 g_WA[8 * 8 * 32];

// ---------------- smem byte offsets ----------------
#define OFF_B    0        // r fp16, B-fragment order (swizzled): 32768 B
#define OFF_RBF  32768    // rbf tile [128][8] f32 (padded): 4096 B
#define OFF_XI   36864    // 512 B
#define OFF_XJ   37376    // 512 B
#define SMEM_BYTES 37888

// ---------------- helpers ----------------
__device__ __forceinline__ uint32_t smem_u32(const void* p) {
    uint32_t a;
    asm("{ .reg .u64 t; cvta.to.shared.u64 t, %1; cvt.u32.u64 %0, t; }" : "=r"(a) : "l"(p));
    return a;
}
__device__ __forceinline__ uint4 lds128(uint32_t addr) {
    uint4 v;
    asm volatile("ld.shared.v4.b32 {%0,%1,%2,%3}, [%4];"
                 : "=r"(v.x), "=r"(v.y), "=r"(v.z), "=r"(v.w) : "r"(addr));
    return v;
}
__device__ __forceinline__ void sts64(uint32_t addr, u64 v) {
    asm volatile("st.shared.b64 [%0], %1;" :: "r"(addr), "l"(v) : "memory");
}
// packed f16x2: low half <- lo, high half <- hi
__device__ __forceinline__ uint32_t cvt_f16x2(float lo, float hi) {
    uint32_t d;
    asm("cvt.rn.f16x2.f32 %0, %2, %1;" : "=r"(d) : "f"(lo), "f"(hi));
    return d;
}
__device__ __forceinline__ void mma16816(float* d, uint32_t a0, uint32_t a1,
                                         uint32_t a2, uint32_t a3,
                                         uint32_t b0, uint32_t b1) {
    asm volatile(
        "mma.sync.aligned.m16n8k16.row.col.f32.f16.f16.f32 "
        "{%0,%1,%2,%3}, {%4,%5,%6,%7}, {%8,%9}, {%0,%1,%2,%3};"
        : "+f"(d[0]), "+f"(d[1]), "+f"(d[2]), "+f"(d[3])
        : "r"(a0), "r"(a1), "r"(a2), "r"(a3), "r"(b0), "r"(b1));
}
// silu via single-MUFU tanh: z*sigmoid(z) = 0.5z + 0.5z*tanh(0.5z)
__device__ __forceinline__ float silu_t(float z) {
    float h = 0.5f * z;
    float t;
    asm("tanh.approx.f32 %0, %1;" : "=f"(t) : "f"(h));
    return fmaf(h, t, h);
}

// ---------------------------------------------------------------------------
// Single precompute kernel (2 launches/replay keeps ncu -s 5 on edge_mlp).
// ---------------------------------------------------------------------------
__global__ void precompute_all(const float* __restrict__ emb_w,
                               const float* __restrict__ emb_b,
                               const float* __restrict__ lin_w,
                               const float* __restrict__ lin_b) {
    __shared__ float red[2][3][4];
    const int tid = threadIdx.x;
    const int bid = blockIdx.x;

    // ---- part A: u1/u2/c ----
    {
        const int half = tid >> 7;
        const int o = bid * 2 + half;
        const int h = tid & 127;
        float w1 = lin_w[o * (3 * HDIM) + h];
        float w2 = lin_w[o * (3 * HDIM) + HDIM + h];
        float u1 = w1 * emb_w[h];
        float u2 = w2 * emb_w[h];
        float cc = (w1 + w2) * emb_b[h];
        #pragma unroll
        for (int s = 16; s > 0; s >>= 1) {
            u1 += __shfl_down_sync(0xffffffff, u1, s);
            u2 += __shfl_down_sync(0xffffffff, u2, s);
            cc += __shfl_down_sync(0xffffffff, cc, s);
        }
        const int w4 = (tid >> 5) & 3;
        if ((tid & 31) == 0) {
            red[half][0][w4] = u1; red[half][1][w4] = u2; red[half][2][w4] = cc;
        }
        __syncthreads();
        if ((tid & 127) == 0) {
            g_u1[o] = red[half][0][0] + red[half][0][1] + red[half][0][2] + red[half][0][3];
            g_u2[o] = red[half][1][0] + red[half][1][1] + red[half][1][2] + red[half][1][3];
            g_c[o]  = red[half][2][0] + red[half][2][1] + red[half][2][2] + red[half][2][3]
                      + lin_b[o];
        }
    }

    // ---- part B: W3 fp16 A-fragment pack ----
    const int idx = bid * 256 + tid;
    if (idx < 2048) {
        const int lane = idx & 31;
        const int t    = idx >> 5;
        const int tk   = t & 7;
        const int tm   = t >> 3;
        const int o0 = tm * 16 + (lane >> 2);
        const int o1 = o0 + 8;
        const int k0 = tk * 16 + (lane & 3) * 2;

        const float* base = lin_w + 2 * HDIM;
        uint32_t a0 = cvt_f16x2(base[o0 * (3 * HDIM) + k0],     base[o0 * (3 * HDIM) + k0 + 1]);
        uint32_t a1 = cvt_f16x2(base[o1 * (3 * HDIM) + k0],     base[o1 * (3 * HDIM) + k0 + 1]);
        uint32_t a2 = cvt_f16x2(base[o0 * (3 * HDIM) + k0 + 8], base[o0 * (3 * HDIM) + k0 + 9]);
        uint32_t a3 = cvt_f16x2(base[o1 * (3 * HDIM) + k0 + 8], base[o1 * (3 * HDIM) + k0 + 9]);
        g_WA[idx] = make_uint4(a0, a1, a2, a3);
    }
}

// ---------------------------------------------------------------------------
// Main fused kernel
//
// B layout (fp16 r fragments), kt-paired + parity swizzle:
//   pair p = kt>>1, chunk C2 = (e>>3)*4 + p  (64 chunks x 512B)
//   word w = (e&7)*4 + q  (16B words; bytes 0-7 = kt even, 8-15 = kt odd)
//   addr = C2*512 + ((w*16) ^ ((p&1)<<6)) + (kt&1)*8
//   -> store: 2-phase (optimal); load: one LDS.128 feeds two MMAs.
// Epilogue: direct scattered stores (R6 style — no barriers, all warps busy).
// ---------------------------------------------------------------------------
__global__ void __launch_bounds__(256, 2)
edge_mlp_kernel(const float* __restrict__ x,
                const float* __restrict__ rbf,
                const int* __restrict__ iidx,
                const int* __restrict__ jidx,
                const float* __restrict__ rbf_w,
                const float* __restrict__ rbf_b,
                float* __restrict__ out) {
    extern __shared__ char sm[];
    const uint32_t sb = smem_u32(sm);

    const int b    = blockIdx.y;
    const int e0   = blockIdx.x * TILE_E;
    const int tid  = threadIdx.x;
    const int wid  = tid >> 5;
    const int lane = tid & 31;

    float* rbf_s = (float*)(sm + OFF_RBF);   // [128][8] padded
    float* xi_s  = (float*)(sm + OFF_XI);
    float* xj_s  = (float*)(sm + OFF_XJ);

    // ---- stage rbf tile into padded rows [e][8] ----
    {
        const float* src = rbf + ((size_t)b * NEDGE + e0) * NRAD;
        #pragma unroll
        for (int it = 0; it < 3; ++it) {
            int idx = tid + it * 256;        // 0..767
            int e = idx / NRAD, m = idx - e * NRAD;
            rbf_s[e * 8 + m] = src[idx];
        }
    }
    // ---- gather x_i / x_j (int32 indices; mask so bad index cannot fault) ----
    if (tid < 128) {
        int e = e0 + tid;
        int ii = iidx[e] & (NNODE - 1);
        int jj = jidx[e] & (NNODE - 1);
        xi_s[tid] = x[b * NNODE + ii];
        xj_s[tid] = x[b * NNODE + jj];
    }
    __syncthreads();

    // ---- r-phase: lane owns 4 k-channels (kb,kb+1,kb+8,kb+9); 16 edges ----
    {
        const int kt = lane >> 2;        // 0..7
        const int q  = lane & 3;         // 0..3
        const int p  = kt >> 1;          // pair 0..3
        const int ph = kt & 1;           // half within pair
        const uint32_t swz = (uint32_t)((p & 1) << 6);
        const int kb = kt * 16 + q * 2;
        const int ks[4] = { kb, kb + 1, kb + 8, kb + 9 };

        float rw[4][NRAD], rb4[4];
        #pragma unroll
        for (int kk = 0; kk < 4; ++kk) {
            rb4[kk] = __ldg(rbf_b + ks[kk]);
            #pragma unroll
            for (int m = 0; m < NRAD; ++m)
                rw[kk][m] = __ldg(rbf_w + ks[kk] * NRAD + m);
        }

        const int ebase = wid * 16;
        #pragma unroll 2
        for (int t = 0; t < 16; ++t) {
            const int e = ebase + t;
            const float4 r03 = *(const float4*)(rbf_s + e * 8);
            const float2 r45 = *(const float2*)(rbf_s + e * 8 + 4);
            const float rv[NRAD] = { r03.x, r03.y, r03.z, r03.w, r45.x, r45.y };

            float z[4];
            #pragma unroll
            for (int kk = 0; kk < 4; ++kk) {
                z[kk] = rb4[kk];
                #pragma unroll
                for (int m = 0; m < NRAD; ++m)
                    z[kk] = fmaf(rv[m], rw[kk][m], z[kk]);
            }
            uint32_t b01 = cvt_f16x2(silu_t(z[0]), silu_t(z[1]));
            uint32_t b23 = cvt_f16x2(silu_t(z[2]), silu_t(z[3]));

            const uint32_t C2 = (uint32_t)(((e >> 3) * 4 + p));
            const uint32_t w  = (uint32_t)(((e & 7) * 4 + q));
            uint32_t addr = sb + OFF_B + C2 * 512 + ((w * 16) ^ swz) + ph * 8;
            sts64(addr, (u64)b01 | ((u64)b23 << 32));
        }
    }
    __syncthreads();

    // ---- mma: warp tile 32(o) x 64(e); LDS.128 feeds two MMAs ----
    const int wm  = wid & 3;    // o-group: rows wm*32..+31
    const int wng = wid >> 2;   // e-group: cols wng*64..+63

    float acc[2][8][4];
    #pragma unroll
    for (int i = 0; i < 2; ++i)
        #pragma unroll
        for (int j = 0; j < 8; ++j)
            #pragma unroll
            for (int q = 0; q < 4; ++q) acc[i][j][q] = 0.f;

    #pragma unroll
    for (int p = 0; p < 4; ++p) {
        const int kt0 = 2 * p, kt1 = 2 * p + 1;
        uint4 a0e = __ldg(g_WA + ((wm * 2 + 0) * 8 + kt0) * 32 + lane);
        uint4 a0o = __ldg(g_WA + ((wm * 2 + 0) * 8 + kt1) * 32 + lane);
        uint4 a1e = __ldg(g_WA + ((wm * 2 + 1) * 8 + kt0) * 32 + lane);
        uint4 a1o = __ldg(g_WA + ((wm * 2 + 1) * 8 + kt1) * 32 + lane);
        const uint32_t swz = (uint32_t)((p & 1) << 6);
        #pragma unroll
        for (int j = 0; j < 8; ++j) {
            const uint32_t C2 = (uint32_t)(((wng * 8 + j) * 4 + p));
            uint4 v = lds128(sb + OFF_B + C2 * 512 + (((uint32_t)lane * 16) ^ swz));
            mma16816(acc[0][j], a0e.x, a0e.y, a0e.z, a0e.w, v.x, v.y);
            mma16816(acc[0][j], a0o.x, a0o.y, a0o.z, a0o.w, v.z, v.w);
            mma16816(acc[1][j], a1e.x, a1e.y, a1e.z, a1e.w, v.x, v.y);
            mma16816(acc[1][j], a1o.x, a1o.y, a1o.z, a1o.w, v.z, v.w);
        }
    }

    // ---- epilogue (direct, R6 style): pre = acc + xi*u1 + xj*u2 + c ----
    // D frag: c0=(o,e) c1=(o,e+1) c2=(o+8,e) c3=(o+8,e+1),
    // o = wm*32 + i*16 + lane>>2, e = wng*64 + j*8 + (lane&3)*2
    float u1v[2][2], u2v[2][2], cv[2][2];
    #pragma unroll
    for (int i = 0; i < 2; ++i) {
        int ob = wm * 32 + i * 16 + (lane >> 2);
        u1v[i][0] = __ldg(g_u1 + ob);     u1v[i][1] = __ldg(g_u1 + ob + 8);
        u2v[i][0] = __ldg(g_u2 + ob);     u2v[i][1] = __ldg(g_u2 + ob + 8);
        cv[i][0]  = __ldg(g_c + ob);      cv[i][1]  = __ldg(g_c + ob + 8);
    }

    float* outb = out + ((size_t)b * NEDGE + e0) * HDIM;
    #pragma unroll
    for (int j = 0; j < 8; ++j) {
        const int eb = wng * 64 + j * 8 + (lane & 3) * 2;
        const float2 xiv = *(const float2*)(xi_s + eb);
        const float2 xjv = *(const float2*)(xj_s + eb);
        #pragma unroll
        for (int i = 0; i < 2; ++i) {
            const int ob = wm * 32 + i * 16 + (lane >> 2);
            #pragma unroll
            for (int h = 0; h < 2; ++h) {           // o vs o+8
                float p0 = acc[i][j][h * 2 + 0];
                float p1 = acc[i][j][h * 2 + 1];
                p0 = fmaf(xiv.x, u1v[i][h], p0);
                p0 = fmaf(xjv.x, u2v[i][h], p0) + cv[i][h];
                p1 = fmaf(xiv.y, u1v[i][h], p1);
                p1 = fmaf(xjv.y, u2v[i][h], p1) + cv[i][h];
                const int oo = ob + h * 8;
                outb[(size_t)eb * HDIM + oo]       = silu_t(p0);
                outb[(size_t)(eb + 1) * HDIM + oo] = silu_t(p1);
            }
        }
    }
}

// ---------------------------------------------------------------------------
extern "C" void kernel_launch(void* const* d_in, const int* in_sizes, int n_in,
                              void* d_out, int out_size) {
    const float* x     = (const float*)d_in[0];
    const float* rbf   = (const float*)d_in[1];
    const int*   iidx  = (const int*)d_in[2];   // int32 (JAX x64 disabled)
    const int*   jidx  = (const int*)d_in[3];
    const float* emb_w = (const float*)d_in[4];
    const float* emb_b = (const float*)d_in[5];
    const float* rbf_w = (const float*)d_in[6];
    const float* rbf_b = (const float*)d_in[7];
    const float* lin_w = (const float*)d_in[8];
    const float* lin_b = (const float*)d_in[9];
    float* out = (float*)d_out;

    precompute_all<<<64, 256>>>(emb_w, emb_b, lin_w, lin_b);

    cudaFuncSetAttribute(edge_mlp_kernel,
                         cudaFuncAttributeMaxDynamicSharedMemorySize, SMEM_BYTES);
    dim3 grid(NEDGE / TILE_E, BATCH);   // (512, 8)
    edge_mlp_kernel<<<grid, 256, SMEM_BYTES>>>(x, rbf, iidx, jidx, rbf_w, rbf_b, out);
}